// round 15
// baseline (speedup 1.0000x reference)
#include <cuda_runtime.h>
#include <cuda_fp16.h>

// ---------------------------------------------------------------------------
// GraphSAGE (2x SAGEConv mean-agg + ReLU + global mean pool).
// Counting-sort by dst (deg hist -> scan -> permute), atomic-free gather
// aggregation (fp32 accumulate), h1 on tensor cores (mma m16n8k16).
//
// This round:
//  - k_permute unrolled x4 (it was latency-bound: issue 3.8%, L2 47%)
//  - x->f16 conversion split into k_convert, run on a FORKED STREAM parallel
//    to the deg/scan/permute chain (event fork-join, capture-legal)
// RULE (cost: 5 rounds): never pass a __device__ symbol's address from host
// code — host shadow symbol + HMM paging = phantom 128MiB allocation.
// ---------------------------------------------------------------------------

#define N_NODES 100000
#define NGRAPHS 128
#define FDIM    64
#define MAX_E   1000000
#define SCAN_BLOCKS 391            // 391*256 >= 100000

__device__ __forceinline__ unsigned int h2_as_u(__half2 h) {
    return *reinterpret_cast<unsigned int*>(&h);
}
__device__ __forceinline__ __half2 u_as_h2(unsigned int u) {
    return *reinterpret_cast<__half2*>(&u);
}

__device__ __align__(16) __half g_x16    [(size_t)N_NODES * FDIM];
__device__ __align__(16) __half g_agg    [(size_t)N_NODES * FDIM];  // mean (both layers)
__device__ __align__(16) __half g_h1     [(size_t)N_NODES * FDIM];
__device__ __align__(16) __half g_scratch[(size_t)N_NODES * FDIM];  // int scratch alias
__device__ float g_pooled[NGRAPHS * 128];  // [g][0:64]=sum h1, [64:128]=sum agg2
__device__ float g_cnt[NGRAPHS];
__device__ int   g_is64;

// scratch layout inside g_scratch (12.8MB; we use ~5.2MB, all 4B-aligned)
__device__ __forceinline__ int* sc_es()   { return (int*)g_scratch; }                 // 1,000,000
__device__ __forceinline__ int* sc_degi() { return ((int*)g_scratch) + 1000000; }     // 100,000
__device__ __forceinline__ int* sc_off()  { return ((int*)g_scratch) + 1100000; }     // 100,001
__device__ __forceinline__ int* sc_cur()  { return ((int*)g_scratch) + 1200004; }     // 100,000
__device__ __forceinline__ int* sc_bsum() { return ((int*)g_scratch) + 1300004; }     // 391

// ---------------------------------------------------------------------------
// Convert x -> f16 (independent of the sort chain; runs on forked stream).
// ---------------------------------------------------------------------------
__global__ void __launch_bounds__(256) k_convert(const float4* __restrict__ x4) {
    size_t stride = (size_t)gridDim.x * blockDim.x;
    size_t t0 = (size_t)blockIdx.x * blockDim.x + threadIdx.x;
    uint4* xh = (uint4*)g_x16;
    const size_t n16 = (size_t)N_NODES * FDIM / 8;
    for (size_t i = t0; i < n16; i += stride) {
        float4 a = x4[2 * i];
        float4 b = x4[2 * i + 1];
        uint4 o;
        o.x = h2_as_u(__floats2half2_rn(a.x, a.y));
        o.y = h2_as_u(__floats2half2_rn(a.z, a.w));
        o.z = h2_as_u(__floats2half2_rn(b.x, b.y));
        o.w = h2_as_u(__floats2half2_rn(b.z, b.w));
        xh[i] = o;
    }
}

// ---------------------------------------------------------------------------
// Degree histogram over dst (degi zero on entry: BSS + consumer-zero in
// scanC). Also publishes is64.
// ---------------------------------------------------------------------------
__global__ void __launch_bounds__(256) k_deg(const void* __restrict__ edge, int E) {
    __shared__ int s_is64;
    if (threadIdx.x == 0) {
        const int* ew = (const int*)edge;
        int is64 = 1;
        #pragma unroll 1
        for (int i = 1; i < 128; i += 2) {
            if (ew[i] != 0) { is64 = 0; break; }
        }
        s_is64 = is64;
        if (blockIdx.x == 0) g_is64 = is64;
    }
    __syncthreads();
    const bool is64 = (s_is64 != 0);

    const long long* ei64 = (const long long*)edge;
    const int*       ei32 = (const int*)edge;
    int* degi = sc_degi();
    int stride = gridDim.x * blockDim.x;
    for (int e = blockIdx.x * blockDim.x + threadIdx.x; e < E; e += stride) {
        int d = is64 ? (int)ei64[E + e] : ei32[E + e];
        atomicAdd(&degi[d], 1);
    }
}

// ---------------------------------------------------------------------------
// scanA: per-block inclusive sums of degi -> bsum[block].
// ---------------------------------------------------------------------------
__global__ void __launch_bounds__(256) k_scanA(void) {
    __shared__ int w[256];
    int n = blockIdx.x * 256 + threadIdx.x;
    int v = (n < N_NODES) ? sc_degi()[n] : 0;
    w[threadIdx.x] = v;
    __syncthreads();
    for (int off = 1; off < 256; off <<= 1) {
        int t = (threadIdx.x >= off) ? w[threadIdx.x - off] : 0;
        __syncthreads();
        w[threadIdx.x] += t;
        __syncthreads();
    }
    if (threadIdx.x == 255) sc_bsum()[blockIdx.x] = w[255];
}

// ---------------------------------------------------------------------------
// scanC: each block redundantly scans the 391 block sums (no scanB kernel),
// scans its 256 degi entries, writes off/cur, zeroes degi for next run.
// ---------------------------------------------------------------------------
__global__ void __launch_bounds__(256) k_scanC(void) {
    __shared__ int w[256];
    __shared__ int bs[512];
    __shared__ int s_base;
    int tid = threadIdx.x;
    int* bsum = sc_bsum();

    int b0 = (tid < SCAN_BLOCKS) ? bsum[tid] : 0;
    int b1 = (tid + 256 < SCAN_BLOCKS) ? bsum[tid + 256] : 0;
    bs[tid] = b0;
    bs[tid + 256] = b1;
    __syncthreads();
    for (int off = 1; off < 512; off <<= 1) {
        int a0 = (tid >= off) ? bs[tid - off] : 0;
        int a1 = (tid + 256 >= off) ? bs[tid + 256 - off] : 0;
        __syncthreads();
        bs[tid] += a0;
        bs[tid + 256] += a1;
        __syncthreads();
    }
    if (tid == 0) {
        int bid = blockIdx.x;
        int incl = bs[bid];
        int own = (bid == 0) ? incl : incl - bs[bid - 1];
        s_base = incl - own;
    }

    int n = blockIdx.x * 256 + tid;
    int v = (n < N_NODES) ? sc_degi()[n] : 0;
    w[tid] = v;
    __syncthreads();
    for (int off = 1; off < 256; off <<= 1) {
        int t = (tid >= off) ? w[tid - off] : 0;
        __syncthreads();
        w[tid] += t;
        __syncthreads();
    }
    if (n < N_NODES) {
        int excl = s_base + w[tid] - v;
        sc_off()[n] = excl;
        sc_cur()[n] = excl;
        sc_degi()[n] = 0;                 // consumer-zero for next run
        if (n == N_NODES - 1) sc_off()[N_NODES] = excl + v;
    }
}

// ---------------------------------------------------------------------------
// Permute: scatter src ids into dst-sorted order. UNROLLED x4: batch the
// edge loads, the returning atomics, and the scattered stores so 4 latency
// chains overlap per thread (kernel was latency-bound, not BW-bound).
// ---------------------------------------------------------------------------
__global__ void __launch_bounds__(256) k_permute(const void* __restrict__ edge, int E) {
    const bool is64 = (g_is64 != 0);
    const long long* ei64 = (const long long*)edge;
    const int*       ei32 = (const int*)edge;
    int* cur = sc_cur();
    int* es  = sc_es();
    int t0 = blockIdx.x * blockDim.x + threadIdx.x;
    int stride = gridDim.x * blockDim.x;

    const int U = 4;
    for (int e0 = t0; e0 < E; e0 += U * stride) {
        int s[U], d[U];
        #pragma unroll
        for (int u = 0; u < U; u++) {
            int e = e0 + u * stride;
            if (e < E) {
                if (is64) { s[u] = (int)ei64[e]; d[u] = (int)ei64[E + e]; }
                else      { s[u] = ei32[e];      d[u] = ei32[E + e]; }
            } else {
                s[u] = -1; d[u] = 0;
            }
        }
        int pos[U];
        #pragma unroll
        for (int u = 0; u < U; u++)
            if (s[u] >= 0) pos[u] = atomicAdd(&cur[d[u]], 1);
        #pragma unroll
        for (int u = 0; u < U; u++)
            if (s[u] >= 0) es[pos[u]] = s[u];
    }
}

// ---------------------------------------------------------------------------
// Aggregate (mean): group of 8 lanes per node; lane owns one uint4 (8 halves).
// Gather src rows (f16), accumulate fp32, write mean back as f16. No atomics.
// Buffers resolved in DEVICE code (phase flag), never host-passed symbols.
// ---------------------------------------------------------------------------
__global__ void __launch_bounds__(256) k_agg(int phase1) {
    const uint4* feat = phase1 ? (const uint4*)g_x16 : (const uint4*)g_h1;
    uint4* out = (uint4*)g_agg;

    int gtid = blockIdx.x * blockDim.x + threadIdx.x;
    int lane8 = gtid & 7;
    int node = gtid >> 3;

    const int* es = sc_es();
    int beg = sc_off()[node], end = sc_off()[node + 1];
    float acc0 = 0.f, acc1 = 0.f, acc2 = 0.f, acc3 = 0.f;
    float acc4 = 0.f, acc5 = 0.f, acc6 = 0.f, acc7 = 0.f;

    int e = beg;
    for (; e + 2 <= end; e += 2) {
        int s0 = es[e], s1 = es[e + 1];
        uint4 v0 = __ldg(&feat[(size_t)s0 * 8 + lane8]);
        uint4 v1 = __ldg(&feat[(size_t)s1 * 8 + lane8]);
        float2 f;
        f = __half22float2(u_as_h2(v0.x)); acc0 += f.x; acc1 += f.y;
        f = __half22float2(u_as_h2(v0.y)); acc2 += f.x; acc3 += f.y;
        f = __half22float2(u_as_h2(v0.z)); acc4 += f.x; acc5 += f.y;
        f = __half22float2(u_as_h2(v0.w)); acc6 += f.x; acc7 += f.y;
        f = __half22float2(u_as_h2(v1.x)); acc0 += f.x; acc1 += f.y;
        f = __half22float2(u_as_h2(v1.y)); acc2 += f.x; acc3 += f.y;
        f = __half22float2(u_as_h2(v1.z)); acc4 += f.x; acc5 += f.y;
        f = __half22float2(u_as_h2(v1.w)); acc6 += f.x; acc7 += f.y;
    }
    if (e < end) {
        int s0 = es[e];
        uint4 v0 = __ldg(&feat[(size_t)s0 * 8 + lane8]);
        float2 f;
        f = __half22float2(u_as_h2(v0.x)); acc0 += f.x; acc1 += f.y;
        f = __half22float2(u_as_h2(v0.y)); acc2 += f.x; acc3 += f.y;
        f = __half22float2(u_as_h2(v0.z)); acc4 += f.x; acc5 += f.y;
        f = __half22float2(u_as_h2(v0.w)); acc6 += f.x; acc7 += f.y;
    }

    float inv = (end > beg) ? 1.0f / (float)(end - beg) : 0.f;
    uint4 o;
    o.x = h2_as_u(__floats2half2_rn(acc0 * inv, acc1 * inv));
    o.y = h2_as_u(__floats2half2_rn(acc2 * inv, acc3 * inv));
    o.z = h2_as_u(__floats2half2_rn(acc4 * inv, acc5 * inv));
    o.w = h2_as_u(__floats2half2_rn(acc6 * inv, acc7 * inv));
    out[(size_t)node * 8 + lane8] = o;
}

// ---------------------------------------------------------------------------
// h1 = relu( [x16 | agg] @ Wc^T + b1 ) on tensor cores (agg is pre-meaned).
// ---------------------------------------------------------------------------
__device__ __forceinline__ void mma16816(
    float& d0, float& d1, float& d2, float& d3,
    unsigned a0, unsigned a1, unsigned a2, unsigned a3,
    unsigned b0, unsigned b1)
{
    asm volatile(
        "mma.sync.aligned.m16n8k16.row.col.f32.f16.f16.f32 "
        "{%0,%1,%2,%3}, {%4,%5,%6,%7}, {%8,%9}, {%0,%1,%2,%3};"
        : "+f"(d0), "+f"(d1), "+f"(d2), "+f"(d3)
        : "r"(a0), "r"(a1), "r"(a2), "r"(a3), "r"(b0), "r"(b1));
}

#define WT_STRIDE 136
#define NTILES (N_NODES / 16)   // 6250, exact

__global__ void __launch_bounds__(256) k_h1(const float* __restrict__ Wl1,
                                            const float* __restrict__ Wr1,
                                            const float* __restrict__ b1) {
    __shared__ __half Wt[64 * WT_STRIDE];  // Wt[c][k], k<64: Wr1, k>=64: Wl1
    __shared__ float bsm[64];

    int tid = threadIdx.x;
    for (int i = tid; i < 64 * 128; i += 256) {
        int c = i >> 7, k = i & 127;
        float v = (k < 64) ? Wr1[c * 64 + k] : Wl1[c * 64 + (k - 64)];
        Wt[c * WT_STRIDE + k] = __float2half(v);
    }
    if (tid < 64) bsm[tid] = b1[tid];
    __syncthreads();

    int lane = tid & 31;
    int g = lane >> 2;        // 0..7
    int t = lane & 3;         // 0..3
    int warp_g = blockIdx.x * 8 + (tid >> 5);
    int nwarps = gridDim.x * 8;

    for (int tile = warp_g; tile < NTILES; tile += nwarps) {
        int nb = tile * 16;
        size_t n0 = (size_t)(nb + g);
        size_t n1 = n0 + 8;

        float acc[8][4];
        #pragma unroll
        for (int j = 0; j < 8; j++)
            #pragma unroll
            for (int q = 0; q < 4; q++) acc[j][q] = 0.f;

        #pragma unroll
        for (int kk = 0; kk < 8; kk++) {
            const __half* base = (kk < 4) ? g_x16 : g_agg;
            int kb = (kk < 4) ? kk * 16 : (kk - 4) * 16;
            unsigned a0 = *(const unsigned*)(base + n0 * 64 + kb + 2 * t);
            unsigned a1 = *(const unsigned*)(base + n1 * 64 + kb + 2 * t);
            unsigned a2 = *(const unsigned*)(base + n0 * 64 + kb + 8 + 2 * t);
            unsigned a3 = *(const unsigned*)(base + n1 * 64 + kb + 8 + 2 * t);
            int kw = kk * 16;
            #pragma unroll
            for (int j = 0; j < 8; j++) {
                unsigned b0 = *(const unsigned*)&Wt[(j * 8 + g) * WT_STRIDE + kw + 2 * t];
                unsigned b1v = *(const unsigned*)&Wt[(j * 8 + g) * WT_STRIDE + kw + 8 + 2 * t];
                mma16816(acc[j][0], acc[j][1], acc[j][2], acc[j][3],
                         a0, a1, a2, a3, b0, b1v);
            }
        }

        #pragma unroll
        for (int j = 0; j < 8; j++) {
            int col = j * 8 + 2 * t;
            float bc0 = bsm[col], bc1 = bsm[col + 1];
            float o0 = fmaxf(acc[j][0] + bc0, 0.f);
            float o1 = fmaxf(acc[j][1] + bc1, 0.f);
            float o2 = fmaxf(acc[j][2] + bc0, 0.f);
            float o3 = fmaxf(acc[j][3] + bc1, 0.f);
            *((__half2*)(g_h1 + n0 * 64 + col)) = __floats2half2_rn(o0, o1);
            *((__half2*)(g_h1 + n1 * 64 + col)) = __floats2half2_rn(o2, o3);
        }
    }
}

// ---------------------------------------------------------------------------
// Pooling: batch sorted -> register accumulate, flush on graph change.
// One WARP per node range: lanes 0-15 -> h1, 16-31 -> agg. Counts nodes.
// pooled/cnt are zero on entry (BSS init + consumer-zero in k_out).
// ---------------------------------------------------------------------------
#define POOL_BLOCKS 1024
__global__ void __launch_bounds__(128) k_pool(const void* __restrict__ batch) {
    const int NW = POOL_BLOCKS * 4;
    int w = blockIdx.x * 4 + (threadIdx.x >> 5);
    int lane = threadIdx.x & 31;
    const bool is64 = (g_is64 != 0);
    const long long* b64 = (const long long*)batch;
    const int*       b32 = (const int*)batch;

    int per = (N_NODES + NW - 1) / NW;
    int start = w * per;
    int end = min(start + per, N_NODES);
    if (start >= end) return;

    const bool isH = lane < 16;
    const int c4 = isH ? lane : (lane - 16);
    const __half* srcbuf = isH ? g_h1 : g_agg;

    float4 acc = make_float4(0.f, 0.f, 0.f, 0.f);
    float ccnt = 0.f;
    int cur = -1;

    for (int n = start; n < end; n++) {
        int g = is64 ? (int)b64[n] : b32[n];
        if (g != cur) {
            if (cur >= 0) {
                float* p = g_pooled + cur * 128 + (isH ? 0 : 64) + c4 * 4;
                atomicAdd(p + 0, acc.x); atomicAdd(p + 1, acc.y);
                atomicAdd(p + 2, acc.z); atomicAdd(p + 3, acc.w);
                if (lane == 0) atomicAdd(&g_cnt[cur], ccnt);
            }
            cur = g;
            acc = make_float4(0.f, 0.f, 0.f, 0.f);
            ccnt = 0.f;
        }
        size_t nn = (size_t)n;
        uint2 raw = *((const uint2*)(srcbuf + nn * 64 + c4 * 4));
        float2 f0 = __half22float2(u_as_h2(raw.x));
        float2 f1 = __half22float2(u_as_h2(raw.y));
        acc.x += f0.x; acc.y += f0.y;
        acc.z += f1.x; acc.w += f1.y;
        ccnt += 1.f;
    }
    float* p = g_pooled + cur * 128 + (isH ? 0 : 64) + c4 * 4;
    atomicAdd(p + 0, acc.x); atomicAdd(p + 1, acc.y);
    atomicAdd(p + 2, acc.z); atomicAdd(p + 3, acc.w);
    if (lane == 0) atomicAdd(&g_cnt[cur], ccnt);
}

// ---------------------------------------------------------------------------
// out[g][c] = b2[c]*[cnt>0] + (P_h1[g]/cnt) . Wr2[c] + (P_ag[g]/cnt) . Wl2[c]
// Also consumer-zeroes pooled/cnt for the next run.
// ---------------------------------------------------------------------------
__global__ void __launch_bounds__(128) k_out(const float* __restrict__ Wl2,
                      const float* __restrict__ Wr2,
                      const float* __restrict__ b2,
                      float* __restrict__ out) {
    int g = blockIdx.x;   // 128
    int c = threadIdx.x;  // 128
    __shared__ float P[128];
    float cntg = g_cnt[g];
    float inv = 1.0f / fmaxf(cntg, 1.0f);
    P[c] = g_pooled[g * 128 + c] * inv;
    __syncthreads();
    g_pooled[g * 128 + c] = 0.f;          // consumer-zero
    if (c == 0) g_cnt[g] = 0.f;

    float acc = (cntg > 0.f) ? b2[c] : 0.f;
    #pragma unroll 8
    for (int k = 0; k < 64; k++) acc += P[k] * Wr2[c * 64 + k];
    #pragma unroll 8
    for (int k = 0; k < 64; k++) acc += P[64 + k] * Wl2[c * 64 + k];
    out[g * 128 + c] = acc;
}

// ---------------------------------------------------------------------------
// Streams/events for the fork-join (created once at program start; no device
// memory allocated inside kernel_launch).
// ---------------------------------------------------------------------------
namespace {
struct ForkCtx {
    cudaStream_t s1;
    cudaEvent_t evFork, evJoin;
    ForkCtx() {
        cudaStreamCreateWithFlags(&s1, cudaStreamNonBlocking);
        cudaEventCreateWithFlags(&evFork, cudaEventDisableTiming);
        cudaEventCreateWithFlags(&evJoin, cudaEventDisableTiming);
    }
};
static ForkCtx s_fork;
}  // namespace

// ---------------------------------------------------------------------------
extern "C" void kernel_launch(void* const* d_in, const int* in_sizes, int n_in,
                              void* d_out, int out_size) {
    const float* x   = (const float*)d_in[0];
    const void*  edge  = d_in[1];
    const void*  batch = d_in[2];
    const float* Wl1 = (const float*)d_in[3];
    const float* Wr1 = (const float*)d_in[4];
    const float* b1  = (const float*)d_in[5];
    const float* Wl2 = (const float*)d_in[6];
    const float* Wr2 = (const float*)d_in[7];
    const float* b2  = (const float*)d_in[8];
    float* out = (float*)d_out;

    int E = in_sizes[1] / 2;
    if (E > MAX_E) E = MAX_E;

    // fork: x->f16 conversion runs parallel to the sort chain
    cudaEventRecord(s_fork.evFork, 0);
    cudaStreamWaitEvent(s_fork.s1, s_fork.evFork, 0);
    k_convert<<<1024, 256, 0, s_fork.s1>>>((const float4*)x);

    k_deg<<<1024, 256>>>(edge, E);
    k_scanA<<<SCAN_BLOCKS, 256>>>();
    k_scanC<<<SCAN_BLOCKS, 256>>>();
    k_permute<<<2048, 256>>>(edge, E);

    // join before first aggregation (needs g_x16)
    cudaEventRecord(s_fork.evJoin, s_fork.s1);
    cudaStreamWaitEvent(0, s_fork.evJoin, 0);

    k_agg<<<3125, 256>>>(1);
    k_h1<<<296, 256>>>(Wl1, Wr1, b1);
    k_agg<<<3125, 256>>>(0);
    k_pool<<<POOL_BLOCKS, 128>>>(batch);
    k_out<<<NGRAPHS, 128>>>(Wl2, Wr2, b2, out);
}

// round 16
// speedup vs baseline: 1.0330x; 1.0330x over previous
#include <cuda_runtime.h>
#include <cuda_fp16.h>

// ---------------------------------------------------------------------------
// GraphSAGE (2x SAGEConv mean-agg + ReLU + global mean pool).
// Counting-sort by dst (deg hist -> scan -> permute), atomic-free gather
// aggregation (fp32 accumulate), h1 on tensor cores (mma m16n8k16).
//
// R16 = R14 (best, 112.6us) + x4-unrolled k_permute (proven winner in R15).
// Fork-join stream overlap REVERTED (R15 showed it costs ~14us under capture).
// RULE (cost: 5 rounds): never pass a __device__ symbol's address from host
// code — host shadow symbol + HMM paging = phantom 128MiB allocation.
// ---------------------------------------------------------------------------

#define N_NODES 100000
#define NGRAPHS 128
#define FDIM    64
#define MAX_E   1000000
#define SCAN_BLOCKS 391            // 391*256 >= 100000

__device__ __forceinline__ unsigned int h2_as_u(__half2 h) {
    return *reinterpret_cast<unsigned int*>(&h);
}
__device__ __forceinline__ __half2 u_as_h2(unsigned int u) {
    return *reinterpret_cast<__half2*>(&u);
}

__device__ __align__(16) __half g_x16    [(size_t)N_NODES * FDIM];
__device__ __align__(16) __half g_agg    [(size_t)N_NODES * FDIM];  // mean (both layers)
__device__ __align__(16) __half g_h1     [(size_t)N_NODES * FDIM];
__device__ __align__(16) __half g_scratch[(size_t)N_NODES * FDIM];  // int scratch alias
__device__ float g_pooled[NGRAPHS * 128];  // [g][0:64]=sum h1, [64:128]=sum agg2
__device__ float g_cnt[NGRAPHS];
__device__ int   g_is64;

// scratch layout inside g_scratch (12.8MB; we use ~5.2MB, all 4B-aligned)
__device__ __forceinline__ int* sc_es()   { return (int*)g_scratch; }                 // 1,000,000
__device__ __forceinline__ int* sc_degi() { return ((int*)g_scratch) + 1000000; }     // 100,000
__device__ __forceinline__ int* sc_off()  { return ((int*)g_scratch) + 1100000; }     // 100,001
__device__ __forceinline__ int* sc_cur()  { return ((int*)g_scratch) + 1200004; }     // 100,000
__device__ __forceinline__ int* sc_bsum() { return ((int*)g_scratch) + 1300004; }     // 391

// ---------------------------------------------------------------------------
// Prep: convert x -> f16, degree histogram over dst (degi is zero on entry:
// BSS-zeroed at load, re-zeroed by scanC every run), detect index width.
// ---------------------------------------------------------------------------
__global__ void __launch_bounds__(256) k_prep(const float4* __restrict__ x4,
                                              const void* __restrict__ edge, int E) {
    __shared__ int s_is64;
    if (threadIdx.x == 0) {
        const int* ew = (const int*)edge;
        int is64 = 1;
        #pragma unroll 1
        for (int i = 1; i < 128; i += 2) {
            if (ew[i] != 0) { is64 = 0; break; }
        }
        s_is64 = is64;
        if (blockIdx.x == 0) g_is64 = is64;
    }
    __syncthreads();
    const bool is64 = (s_is64 != 0);

    size_t stride = (size_t)gridDim.x * blockDim.x;
    size_t t0 = (size_t)blockIdx.x * blockDim.x + threadIdx.x;
    uint4* xh = (uint4*)g_x16;
    const size_t n16 = (size_t)N_NODES * FDIM / 8;

    for (size_t i = t0; i < n16; i += stride) {
        float4 a = x4[2 * i];
        float4 b = x4[2 * i + 1];
        uint4 o;
        o.x = h2_as_u(__floats2half2_rn(a.x, a.y));
        o.y = h2_as_u(__floats2half2_rn(a.z, a.w));
        o.z = h2_as_u(__floats2half2_rn(b.x, b.y));
        o.w = h2_as_u(__floats2half2_rn(b.z, b.w));
        xh[i] = o;
    }

    const long long* ei64 = (const long long*)edge;
    const int*       ei32 = (const int*)edge;
    int* degi = sc_degi();
    for (int e = (int)t0; e < E; e += (int)stride) {
        int d = is64 ? (int)ei64[E + e] : ei32[E + e];
        atomicAdd(&degi[d], 1);
    }
}

// ---------------------------------------------------------------------------
// scanA: per-block inclusive sums of degi -> bsum[block].
// ---------------------------------------------------------------------------
__global__ void __launch_bounds__(256) k_scanA(void) {
    __shared__ int w[256];
    int n = blockIdx.x * 256 + threadIdx.x;
    int v = (n < N_NODES) ? sc_degi()[n] : 0;
    w[threadIdx.x] = v;
    __syncthreads();
    for (int off = 1; off < 256; off <<= 1) {
        int t = (threadIdx.x >= off) ? w[threadIdx.x - off] : 0;
        __syncthreads();
        w[threadIdx.x] += t;
        __syncthreads();
    }
    if (threadIdx.x == 255) sc_bsum()[blockIdx.x] = w[255];
}

// ---------------------------------------------------------------------------
// scanC: each block redundantly scans the 391 block sums (no scanB kernel),
// scans its 256 degi entries, writes off/cur, zeroes degi for next run.
// ---------------------------------------------------------------------------
__global__ void __launch_bounds__(256) k_scanC(void) {
    __shared__ int w[256];
    __shared__ int bs[512];
    __shared__ int s_base;
    int tid = threadIdx.x;
    int* bsum = sc_bsum();

    int b0 = (tid < SCAN_BLOCKS) ? bsum[tid] : 0;
    int b1 = (tid + 256 < SCAN_BLOCKS) ? bsum[tid + 256] : 0;
    bs[tid] = b0;
    bs[tid + 256] = b1;
    __syncthreads();
    for (int off = 1; off < 512; off <<= 1) {
        int a0 = (tid >= off) ? bs[tid - off] : 0;
        int a1 = (tid + 256 >= off) ? bs[tid + 256 - off] : 0;
        __syncthreads();
        bs[tid] += a0;
        bs[tid + 256] += a1;
        __syncthreads();
    }
    if (tid == 0) {
        int bid = blockIdx.x;
        int incl = bs[bid];
        int own = (bid == 0) ? incl : incl - bs[bid - 1];
        s_base = incl - own;
    }

    int n = blockIdx.x * 256 + tid;
    int v = (n < N_NODES) ? sc_degi()[n] : 0;
    w[tid] = v;
    __syncthreads();
    for (int off = 1; off < 256; off <<= 1) {
        int t = (tid >= off) ? w[tid - off] : 0;
        __syncthreads();
        w[tid] += t;
        __syncthreads();
    }
    if (n < N_NODES) {
        int excl = s_base + w[tid] - v;
        sc_off()[n] = excl;
        sc_cur()[n] = excl;
        sc_degi()[n] = 0;                 // consumer-zero for next run
        if (n == N_NODES - 1) sc_off()[N_NODES] = excl + v;
    }
}

// ---------------------------------------------------------------------------
// Permute: scatter src ids into dst-sorted order. UNROLLED x4 (proven in
// R15: latency-bound, batching the edge loads / returning atomics / stores
// overlaps 4 latency chains per thread).
// ---------------------------------------------------------------------------
__global__ void __launch_bounds__(256) k_permute(const void* __restrict__ edge, int E) {
    const bool is64 = (g_is64 != 0);
    const long long* ei64 = (const long long*)edge;
    const int*       ei32 = (const int*)edge;
    int* cur = sc_cur();
    int* es  = sc_es();
    int t0 = blockIdx.x * blockDim.x + threadIdx.x;
    int stride = gridDim.x * blockDim.x;

    const int U = 4;
    for (int e0 = t0; e0 < E; e0 += U * stride) {
        int s[U], d[U];
        #pragma unroll
        for (int u = 0; u < U; u++) {
            int e = e0 + u * stride;
            if (e < E) {
                if (is64) { s[u] = (int)ei64[e]; d[u] = (int)ei64[E + e]; }
                else      { s[u] = ei32[e];      d[u] = ei32[E + e]; }
            } else {
                s[u] = -1; d[u] = 0;
            }
        }
        int pos[U];
        #pragma unroll
        for (int u = 0; u < U; u++)
            if (s[u] >= 0) pos[u] = atomicAdd(&cur[d[u]], 1);
        #pragma unroll
        for (int u = 0; u < U; u++)
            if (s[u] >= 0) es[pos[u]] = s[u];
    }
}

// ---------------------------------------------------------------------------
// Aggregate (mean): group of 8 lanes per node; lane owns one uint4 (8 halves).
// Gather src rows (f16), accumulate fp32, write mean back as f16. No atomics.
// Buffers resolved in DEVICE code (phase flag), never host-passed symbols.
// ---------------------------------------------------------------------------
__global__ void __launch_bounds__(256) k_agg(int phase1) {
    const uint4* feat = phase1 ? (const uint4*)g_x16 : (const uint4*)g_h1;
    uint4* out = (uint4*)g_agg;

    int gtid = blockIdx.x * blockDim.x + threadIdx.x;
    int lane8 = gtid & 7;
    int node = gtid >> 3;

    const int* es = sc_es();
    int beg = sc_off()[node], end = sc_off()[node + 1];
    float acc0 = 0.f, acc1 = 0.f, acc2 = 0.f, acc3 = 0.f;
    float acc4 = 0.f, acc5 = 0.f, acc6 = 0.f, acc7 = 0.f;

    int e = beg;
    for (; e + 2 <= end; e += 2) {
        int s0 = es[e], s1 = es[e + 1];
        uint4 v0 = __ldg(&feat[(size_t)s0 * 8 + lane8]);
        uint4 v1 = __ldg(&feat[(size_t)s1 * 8 + lane8]);
        float2 f;
        f = __half22float2(u_as_h2(v0.x)); acc0 += f.x; acc1 += f.y;
        f = __half22float2(u_as_h2(v0.y)); acc2 += f.x; acc3 += f.y;
        f = __half22float2(u_as_h2(v0.z)); acc4 += f.x; acc5 += f.y;
        f = __half22float2(u_as_h2(v0.w)); acc6 += f.x; acc7 += f.y;
        f = __half22float2(u_as_h2(v1.x)); acc0 += f.x; acc1 += f.y;
        f = __half22float2(u_as_h2(v1.y)); acc2 += f.x; acc3 += f.y;
        f = __half22float2(u_as_h2(v1.z)); acc4 += f.x; acc5 += f.y;
        f = __half22float2(u_as_h2(v1.w)); acc6 += f.x; acc7 += f.y;
    }
    if (e < end) {
        int s0 = es[e];
        uint4 v0 = __ldg(&feat[(size_t)s0 * 8 + lane8]);
        float2 f;
        f = __half22float2(u_as_h2(v0.x)); acc0 += f.x; acc1 += f.y;
        f = __half22float2(u_as_h2(v0.y)); acc2 += f.x; acc3 += f.y;
        f = __half22float2(u_as_h2(v0.z)); acc4 += f.x; acc5 += f.y;
        f = __half22float2(u_as_h2(v0.w)); acc6 += f.x; acc7 += f.y;
    }

    float inv = (end > beg) ? 1.0f / (float)(end - beg) : 0.f;
    uint4 o;
    o.x = h2_as_u(__floats2half2_rn(acc0 * inv, acc1 * inv));
    o.y = h2_as_u(__floats2half2_rn(acc2 * inv, acc3 * inv));
    o.z = h2_as_u(__floats2half2_rn(acc4 * inv, acc5 * inv));
    o.w = h2_as_u(__floats2half2_rn(acc6 * inv, acc7 * inv));
    out[(size_t)node * 8 + lane8] = o;
}

// ---------------------------------------------------------------------------
// h1 = relu( [x16 | agg] @ Wc^T + b1 ) on tensor cores (agg is pre-meaned).
// ---------------------------------------------------------------------------
__device__ __forceinline__ void mma16816(
    float& d0, float& d1, float& d2, float& d3,
    unsigned a0, unsigned a1, unsigned a2, unsigned a3,
    unsigned b0, unsigned b1)
{
    asm volatile(
        "mma.sync.aligned.m16n8k16.row.col.f32.f16.f16.f32 "
        "{%0,%1,%2,%3}, {%4,%5,%6,%7}, {%8,%9}, {%0,%1,%2,%3};"
        : "+f"(d0), "+f"(d1), "+f"(d2), "+f"(d3)
        : "r"(a0), "r"(a1), "r"(a2), "r"(a3), "r"(b0), "r"(b1));
}

#define WT_STRIDE 136
#define NTILES (N_NODES / 16)   // 6250, exact

__global__ void __launch_bounds__(256) k_h1(const float* __restrict__ Wl1,
                                            const float* __restrict__ Wr1,
                                            const float* __restrict__ b1) {
    __shared__ __half Wt[64 * WT_STRIDE];  // Wt[c][k], k<64: Wr1, k>=64: Wl1
    __shared__ float bsm[64];

    int tid = threadIdx.x;
    for (int i = tid; i < 64 * 128; i += 256) {
        int c = i >> 7, k = i & 127;
        float v = (k < 64) ? Wr1[c * 64 + k] : Wl1[c * 64 + (k - 64)];
        Wt[c * WT_STRIDE + k] = __float2half(v);
    }
    if (tid < 64) bsm[tid] = b1[tid];
    __syncthreads();

    int lane = tid & 31;
    int g = lane >> 2;        // 0..7
    int t = lane & 3;         // 0..3
    int warp_g = blockIdx.x * 8 + (tid >> 5);
    int nwarps = gridDim.x * 8;

    for (int tile = warp_g; tile < NTILES; tile += nwarps) {
        int nb = tile * 16;
        size_t n0 = (size_t)(nb + g);
        size_t n1 = n0 + 8;

        float acc[8][4];
        #pragma unroll
        for (int j = 0; j < 8; j++)
            #pragma unroll
            for (int q = 0; q < 4; q++) acc[j][q] = 0.f;

        #pragma unroll
        for (int kk = 0; kk < 8; kk++) {
            const __half* base = (kk < 4) ? g_x16 : g_agg;
            int kb = (kk < 4) ? kk * 16 : (kk - 4) * 16;
            unsigned a0 = *(const unsigned*)(base + n0 * 64 + kb + 2 * t);
            unsigned a1 = *(const unsigned*)(base + n1 * 64 + kb + 2 * t);
            unsigned a2 = *(const unsigned*)(base + n0 * 64 + kb + 8 + 2 * t);
            unsigned a3 = *(const unsigned*)(base + n1 * 64 + kb + 8 + 2 * t);
            int kw = kk * 16;
            #pragma unroll
            for (int j = 0; j < 8; j++) {
                unsigned b0 = *(const unsigned*)&Wt[(j * 8 + g) * WT_STRIDE + kw + 2 * t];
                unsigned b1v = *(const unsigned*)&Wt[(j * 8 + g) * WT_STRIDE + kw + 8 + 2 * t];
                mma16816(acc[j][0], acc[j][1], acc[j][2], acc[j][3],
                         a0, a1, a2, a3, b0, b1v);
            }
        }

        #pragma unroll
        for (int j = 0; j < 8; j++) {
            int col = j * 8 + 2 * t;
            float bc0 = bsm[col], bc1 = bsm[col + 1];
            float o0 = fmaxf(acc[j][0] + bc0, 0.f);
            float o1 = fmaxf(acc[j][1] + bc1, 0.f);
            float o2 = fmaxf(acc[j][2] + bc0, 0.f);
            float o3 = fmaxf(acc[j][3] + bc1, 0.f);
            *((__half2*)(g_h1 + n0 * 64 + col)) = __floats2half2_rn(o0, o1);
            *((__half2*)(g_h1 + n1 * 64 + col)) = __floats2half2_rn(o2, o3);
        }
    }
}

// ---------------------------------------------------------------------------
// Pooling: batch sorted -> register accumulate, flush on graph change.
// One WARP per node range: lanes 0-15 -> h1, 16-31 -> agg. Counts nodes.
// pooled/cnt are zero on entry (BSS init + consumer-zero in k_out).
// ---------------------------------------------------------------------------
#define POOL_BLOCKS 1024
__global__ void __launch_bounds__(128) k_pool(const void* __restrict__ batch) {
    const int NW = POOL_BLOCKS * 4;
    int w = blockIdx.x * 4 + (threadIdx.x >> 5);
    int lane = threadIdx.x & 31;
    const bool is64 = (g_is64 != 0);
    const long long* b64 = (const long long*)batch;
    const int*       b32 = (const int*)batch;

    int per = (N_NODES + NW - 1) / NW;
    int start = w * per;
    int end = min(start + per, N_NODES);
    if (start >= end) return;

    const bool isH = lane < 16;
    const int c4 = isH ? lane : (lane - 16);
    const __half* srcbuf = isH ? g_h1 : g_agg;

    float4 acc = make_float4(0.f, 0.f, 0.f, 0.f);
    float ccnt = 0.f;
    int cur = -1;

    for (int n = start; n < end; n++) {
        int g = is64 ? (int)b64[n] : b32[n];
        if (g != cur) {
            if (cur >= 0) {
                float* p = g_pooled + cur * 128 + (isH ? 0 : 64) + c4 * 4;
                atomicAdd(p + 0, acc.x); atomicAdd(p + 1, acc.y);
                atomicAdd(p + 2, acc.z); atomicAdd(p + 3, acc.w);
                if (lane == 0) atomicAdd(&g_cnt[cur], ccnt);
            }
            cur = g;
            acc = make_float4(0.f, 0.f, 0.f, 0.f);
            ccnt = 0.f;
        }
        size_t nn = (size_t)n;
        uint2 raw = *((const uint2*)(srcbuf + nn * 64 + c4 * 4));
        float2 f0 = __half22float2(u_as_h2(raw.x));
        float2 f1 = __half22float2(u_as_h2(raw.y));
        acc.x += f0.x; acc.y += f0.y;
        acc.z += f1.x; acc.w += f1.y;
        ccnt += 1.f;
    }
    float* p = g_pooled + cur * 128 + (isH ? 0 : 64) + c4 * 4;
    atomicAdd(p + 0, acc.x); atomicAdd(p + 1, acc.y);
    atomicAdd(p + 2, acc.z); atomicAdd(p + 3, acc.w);
    if (lane == 0) atomicAdd(&g_cnt[cur], ccnt);
}

// ---------------------------------------------------------------------------
// out[g][c] = b2[c]*[cnt>0] + (P_h1[g]/cnt) . Wr2[c] + (P_ag[g]/cnt) . Wl2[c]
// Also consumer-zeroes pooled/cnt for the next run.
// ---------------------------------------------------------------------------
__global__ void __launch_bounds__(128) k_out(const float* __restrict__ Wl2,
                      const float* __restrict__ Wr2,
                      const float* __restrict__ b2,
                      float* __restrict__ out) {
    int g = blockIdx.x;   // 128
    int c = threadIdx.x;  // 128
    __shared__ float P[128];
    float cntg = g_cnt[g];
    float inv = 1.0f / fmaxf(cntg, 1.0f);
    P[c] = g_pooled[g * 128 + c] * inv;
    __syncthreads();
    g_pooled[g * 128 + c] = 0.f;          // consumer-zero
    if (c == 0) g_cnt[g] = 0.f;

    float acc = (cntg > 0.f) ? b2[c] : 0.f;
    #pragma unroll 8
    for (int k = 0; k < 64; k++) acc += P[k] * Wr2[c * 64 + k];
    #pragma unroll 8
    for (int k = 0; k < 64; k++) acc += P[64 + k] * Wl2[c * 64 + k];
    out[g * 128 + c] = acc;
}

// ---------------------------------------------------------------------------
extern "C" void kernel_launch(void* const* d_in, const int* in_sizes, int n_in,
                              void* d_out, int out_size) {
    const float* x   = (const float*)d_in[0];
    const void*  edge  = d_in[1];
    const void*  batch = d_in[2];
    const float* Wl1 = (const float*)d_in[3];
    const float* Wr1 = (const float*)d_in[4];
    const float* b1  = (const float*)d_in[5];
    const float* Wl2 = (const float*)d_in[6];
    const float* Wr2 = (const float*)d_in[7];
    const float* b2  = (const float*)d_in[8];
    float* out = (float*)d_out;

    int E = in_sizes[1] / 2;
    if (E > MAX_E) E = MAX_E;

    k_prep<<<2048, 256>>>((const float4*)x, edge, E);
    k_scanA<<<SCAN_BLOCKS, 256>>>();
    k_scanC<<<SCAN_BLOCKS, 256>>>();
    k_permute<<<2048, 256>>>(edge, E);
    k_agg<<<3125, 256>>>(1);
    k_h1<<<296, 256>>>(Wl1, Wr1, b1);
    k_agg<<<3125, 256>>>(0);
    k_pool<<<POOL_BLOCKS, 128>>>(batch);
    k_out<<<NGRAPHS, 128>>>(Wl2, Wr2, b2, out);
}